// round 15
// baseline (speedup 1.0000x reference)
#include <cuda_runtime.h>
#include <cuda_fp16.h>
#include <cstdint>
#include <math.h>

#define BB 8
#define LLEN 2048
#define DDIM 1024
#define MTOT (BB * LLEN)          // 16384

// ---------------------------------------------------------------------------
// Scratch (__device__ globals; allocation-free per harness rules)
// ---------------------------------------------------------------------------
__device__ __half g_q16[MTOT * DDIM], g_k16[MTOT * DDIM], g_v16[MTOT * DDIM];
__device__ __half g_WqT[DDIM * DDIM], g_WkT[DDIM * DDIM], g_WvT[DDIM * DDIM];
__device__ __half g_WgT[DDIM * 2 * DDIM];
__device__ __half g_qp[MTOT * DDIM], g_kp[MTOT * DDIM], g_vp[MTOT * DDIM];
__device__ __half g_vpT[MTOT * DDIM];
__device__ __half g_S16[BB * LLEN * LLEN];        // 67 MB
__device__ __half g_P[BB * LLEN * LLEN];          // 67 MB
__device__ __half g_x16[MTOT * DDIM];

// ---------------------------------------------------------------------------
// helpers
// ---------------------------------------------------------------------------
__device__ __forceinline__ uint32_t smem_u32(const void* p) {
    uint32_t a;
    asm("{ .reg .u64 t; cvta.to.shared.u64 t, %1; cvt.u32.u64 %0, t; }"
        : "=r"(a) : "l"(p));
    return a;
}
__device__ __forceinline__ void cp16(uint32_t d, const void* s) {
    asm volatile("cp.async.cg.shared.global [%0], [%1], 16;"
                 :: "r"(d), "l"(s) : "memory");
}
__device__ __forceinline__ void cp_commit() {
    asm volatile("cp.async.commit_group;" ::: "memory");
}
template <int N>
__device__ __forceinline__ void cp_wait() {
    asm volatile("cp.async.wait_group %0;" :: "n"(N) : "memory");
}
__device__ __forceinline__ void ldsm4(uint32_t addr, uint32_t* r) {
    asm volatile("ldmatrix.sync.aligned.m8n8.x4.shared.b16 {%0,%1,%2,%3}, [%4];"
                 : "=r"(r[0]), "=r"(r[1]), "=r"(r[2]), "=r"(r[3]) : "r"(addr));
}
__device__ __forceinline__ void mma16816(float* c, const uint32_t* a,
                                         uint32_t b0, uint32_t b1) {
    asm volatile(
        "mma.sync.aligned.m16n8k16.row.col.f32.f16.f16.f32 "
        "{%0,%1,%2,%3}, {%4,%5,%6,%7}, {%8,%9}, {%0,%1,%2,%3};"
        : "+f"(c[0]), "+f"(c[1]), "+f"(c[2]), "+f"(c[3])
        : "r"(a[0]), "r"(a[1]), "r"(a[2]), "r"(a[3]), "r"(b0), "r"(b1));
}

#define SWZ(o) ((o) ^ (((o) >> 3) & 0x70))

__device__ __forceinline__ uint32_t h2pack(float a, float b) {
    __half2 h = __floats2half2_rn(a, b);
    return *(uint32_t*)&h;
}

// ---------------------------------------------------------------------------
// fp16 HMMA GEMM: C[M,N] = epi( A[M,K] @ B[N,K]^T )   [R7-proven mainloop]
//   CTA tile 128x128, BK=64, 3-stage cp.async pipeline, 8 warps (32x64 each),
//   2 CTAs/SM (4 warps/SMSP).
//   EPI 0: +bias (nullable), write fp16
//   EPI 1: *alpha, write fp16
//   EPI 2: gate: out = x16*mask*sigmoid(acc+bias) + q0, write fp32
// ---------------------------------------------------------------------------
template <int EPI, bool CONCAT>
__global__ __launch_bounds__(256, 2)
void hgemm(const __half* __restrict__ A, const __half* __restrict__ A2,
           int lda, int KA,
           const __half* __restrict__ B, int ldb,
           const float* __restrict__ bias,
           float* __restrict__ Cf, __half* __restrict__ Ch,
           int ldc, int K,
           long long sA, long long sB, long long sC, float alpha,
           const __half* __restrict__ x16, const float* __restrict__ q0,
           const float* __restrict__ mask)
{
    extern __shared__ char dsm[];
    const uint32_t raw = smem_u32(dsm);
    const uint32_t abase = (raw + 1023u) & ~1023u;

    constexpr int TILE = 16384;                 // one 128x64 fp16 tile (swizzled)
    constexpr int OFF_A = 0;                    // 3 stages
    constexpr int OFF_B = 3 * TILE;

    const int tid = threadIdx.x, wid = tid >> 5, lid = tid & 31;
    const int bn = blockIdx.x, bm = blockIdx.y, bz = blockIdx.z;

    A += (long long)bz * sA;
    B += (long long)bz * sB;
    if (EPI == 2) Cf += (long long)bz * sC;
    else          Ch += (long long)bz * sC;

    const int rowA0 = bm * 128, rowB0 = bn * 128;

    auto stage = [&](int kt, int buf) {
        const int r = tid >> 3, seg = tid & 7;
        long long kc = (long long)kt * 64 + seg * 8;
        const __half* pA = A;
        long long kA = kc;
        if (CONCAT && kc >= KA) { pA = A2; kA = kc - KA; }
        #pragma unroll
        for (int i = 0; i < 4; ++i) {
            const int rr = i * 32 + r;
            const uint32_t so = SWZ(rr * 128 + seg * 16);
            cp16(abase + OFF_A + buf * TILE + so, pA + (long long)(rowA0 + rr) * lda + kA);
            cp16(abase + OFF_B + buf * TILE + so, B + (long long)(rowB0 + rr) * ldb + kc);
        }
    };

    const int wm0 = (wid & 3) * 32;     // warp m offset (4 warps over 128)
    const int wn0 = (wid >> 2) * 64;    // warp n offset (2 warps over 128)
    const int r16 = lid & 15, hseg = lid >> 4;

    float acc[2][8][4] = {};

    const int nt = K / 64;
    stage(0, 0); cp_commit();
    stage(1, 1); cp_commit();

    for (int t = 0; t < nt; ++t) {
        if (t + 1 < nt) cp_wait<1>(); else cp_wait<0>();
        __syncthreads();
        if (t + 2 < nt) { stage(t + 2, (t + 2) % 3); cp_commit(); }

        const int buf = t % 3;
        const uint32_t ba = abase + OFF_A + buf * TILE;
        const uint32_t bb = abase + OFF_B + buf * TILE;

        #pragma unroll
        for (int s = 0; s < 4; ++s) {
            uint32_t a[2][4], b[4][4];
            #pragma unroll
            for (int mf = 0; mf < 2; ++mf) {
                const uint32_t o = (uint32_t)((wm0 + mf * 16 + r16) * 128 + s * 32 + hseg * 16);
                ldsm4(ba + SWZ(o), a[mf]);
            }
            #pragma unroll
            for (int g = 0; g < 4; ++g) {
                const uint32_t o = (uint32_t)((wn0 + g * 16 + r16) * 128 + s * 32 + hseg * 16);
                ldsm4(bb + SWZ(o), b[g]);
            }
            #pragma unroll
            for (int mf = 0; mf < 2; ++mf)
                #pragma unroll
                for (int nf = 0; nf < 8; ++nf) {
                    const int g = nf >> 1, o = nf & 1;
                    mma16816(acc[mf][nf], a[mf], b[g][o], b[g][o + 2]);
                }
        }
        // no trailing barrier: next iteration's cp_wait + barrier provide
        // ordering before any staging buffer is overwritten.
    }

    // ------------------- epilogue -------------------
    #pragma unroll
    for (int mf = 0; mf < 2; ++mf) {
        #pragma unroll
        for (int nf = 0; nf < 8; ++nf) {
            const int col = bn * 128 + wn0 + nf * 8 + (lid & 3) * 2;
            #pragma unroll
            for (int h = 0; h < 2; ++h) {
                const int row = bm * 128 + wm0 + mf * 16 + (lid >> 2) + h * 8;
                const long long off = (long long)row * ldc + col;
                float v0 = acc[mf][nf][h * 2 + 0];
                float v1 = acc[mf][nf][h * 2 + 1];

                if (EPI == 0) {
                    if (bias) {
                        const float2 b2 = *(const float2*)(bias + col);
                        v0 += b2.x; v1 += b2.y;
                    }
                    *(uint32_t*)(Ch + off) = h2pack(v0, v1);
                } else if (EPI == 1) {
                    *(uint32_t*)(Ch + off) = h2pack(v0 * alpha, v1 * alpha);
                } else {
                    const float mv = mask[row];
                    const float2 b2 = *(const float2*)(bias + col);
                    const __half2 xh2 = *(const __half2*)(x16 + off);
                    const float2 xf = __half22float2(xh2);
                    const float2 q2 = *(const float2*)(q0 + off);
                    const float g0 = v0 + b2.x, g1 = v1 + b2.y;
                    const float s0 = 1.0f / (1.0f + __expf(-g0));
                    const float s1 = 1.0f / (1.0f + __expf(-g1));
                    *(float2*)(Cf + off) = make_float2(xf.x * mv * s0 + q2.x,
                                                       xf.y * mv * s1 + q2.y);
                }
            }
        }
    }
}

// ---------------------------------------------------------------------------
// fp32 -> fp16 convert (elementwise, 4/thread)
// ---------------------------------------------------------------------------
__global__ __launch_bounds__(256)
void conv_k(const float* __restrict__ X, __half* __restrict__ H)
{
    const long long i = ((long long)blockIdx.x * 256 + threadIdx.x) * 4;
    float4 v = *(const float4*)(X + i);
    uint2 o;
    o.x = h2pack(v.x, v.y);
    o.y = h2pack(v.z, v.w);
    *(uint2*)(H + i) = o;
}

// W[R,C] fp32 -> T[C,R] fp16 (transpose + convert)
__global__ __launch_bounds__(256)
void transpose_conv_k(const float* __restrict__ W, __half* __restrict__ T,
                      int R, int C)
{
    __shared__ float tile[32][33];
    const int tx = threadIdx.x, ty = threadIdx.y;
    const int x = blockIdx.x * 32 + tx;
    const int y0 = blockIdx.y * 32;
    #pragma unroll
    for (int j = ty; j < 32; j += 8)
        tile[j][tx] = W[(long long)(y0 + j) * C + x];
    __syncthreads();
    const int ox = y0 + tx;
    const int oy0 = blockIdx.x * 32;
    #pragma unroll
    for (int j = ty; j < 32; j += 8)
        T[(long long)(oy0 + j) * R + ox] = __float2half_rn(tile[tx][j]);
}

// fp16 transpose: X[R,C] -> T[C,R]
__global__ __launch_bounds__(256)
void transpose_h_k(const __half* __restrict__ X, __half* __restrict__ T,
                   int R, int C)
{
    __shared__ __half tile[32][34];
    const int tx = threadIdx.x, ty = threadIdx.y;
    const int x = blockIdx.x * 32 + tx;
    const int y0 = blockIdx.y * 32;
    #pragma unroll
    for (int j = ty; j < 32; j += 8)
        tile[j][tx] = X[(long long)(y0 + j) * C + x];
    __syncthreads();
    const int ox = y0 + tx;
    const int oy0 = blockIdx.x * 32;
    #pragma unroll
    for (int j = ty; j < 32; j += 8)
        T[(long long)(oy0 + j) * R + ox] = tile[tx][j];
}

// Row softmax over S16 (rows of 2048 fp16) -> P fp16.
// Fully vectorized: each thread owns 8 contiguous halves (one uint4).
__global__ __launch_bounds__(256)
void softmax_h_k(const __half* __restrict__ S, __half* __restrict__ P)
{
    const long long base = (long long)blockIdx.x * LLEN;
    const int tid = threadIdx.x;

    uint4 pk = *(const uint4*)(S + base + tid * 8);
    float v[8];
    {
        const uint32_t w[4] = {pk.x, pk.y, pk.z, pk.w};
        #pragma unroll
        for (int j = 0; j < 4; ++j) {
            const float2 f = __half22float2(*(const __half2*)&w[j]);
            v[2 * j] = f.x; v[2 * j + 1] = f.y;
        }
    }

    float mx = v[0];
    #pragma unroll
    for (int i = 1; i < 8; ++i) mx = fmaxf(mx, v[i]);
    #pragma unroll
    for (int o = 16; o > 0; o >>= 1)
        mx = fmaxf(mx, __shfl_xor_sync(0xffffffffu, mx, o));

    __shared__ float red[8];
    if ((tid & 31) == 0) red[tid >> 5] = mx;
    __syncthreads();
    mx = red[0];
    #pragma unroll
    for (int i = 1; i < 8; ++i) mx = fmaxf(mx, red[i]);
    __syncthreads();

    float s = 0.0f;
    #pragma unroll
    for (int i = 0; i < 8; ++i) { v[i] = __expf(v[i] - mx); s += v[i]; }
    #pragma unroll
    for (int o = 16; o > 0; o >>= 1)
        s += __shfl_xor_sync(0xffffffffu, s, o);
    if ((tid & 31) == 0) red[tid >> 5] = s;
    __syncthreads();
    s = 0.0f;
    #pragma unroll
    for (int i = 0; i < 8; ++i) s += red[i];

    const float inv = 1.0f / s;
    uint4 out;
    out.x = h2pack(v[0] * inv, v[1] * inv);
    out.y = h2pack(v[2] * inv, v[3] * inv);
    out.z = h2pack(v[4] * inv, v[5] * inv);
    out.w = h2pack(v[6] * inv, v[7] * inv);
    *(uint4*)(P + base + tid * 8) = out;
}

// ---------------------------------------------------------------------------
// Host
// ---------------------------------------------------------------------------
extern "C" void kernel_launch(void* const* d_in, const int* in_sizes, int n_in,
                              void* d_out, int out_size)
{
    const float* q    = (const float*)d_in[0];
    const float* k    = (const float*)d_in[1];
    const float* v    = (const float*)d_in[2];
    const float* mask = (const float*)d_in[3];
    const float* Wq   = (const float*)d_in[4];
    const float* bq   = (const float*)d_in[5];
    const float* Wk   = (const float*)d_in[6];
    const float* bk   = (const float*)d_in[7];
    const float* Wv   = (const float*)d_in[8];
    const float* bv   = (const float*)d_in[9];
    const float* Wg   = (const float*)d_in[10];
    const float* bg   = (const float*)d_in[11];
    float* out = (float*)d_out;

    #define SYM(p, s) void* p##_; cudaGetSymbolAddress(&p##_, s); \
                      __half* p = (__half*)p##_;
    SYM(q16, g_q16) SYM(k16, g_k16) SYM(v16, g_v16)
    SYM(WqT, g_WqT) SYM(WkT, g_WkT) SYM(WvT, g_WvT) SYM(WgT, g_WgT)
    SYM(qp, g_qp)   SYM(kp, g_kp)   SYM(vp, g_vp)   SYM(vpT, g_vpT)
    SYM(S16, g_S16) SYM(P, g_P)     SYM(x16, g_x16)
    #undef SYM

    const int SMEM_DYN = 6 * 16384 + 1024;   // 3 stages x (A+B) + align pad
    cudaFuncSetAttribute(hgemm<0, false>, cudaFuncAttributeMaxDynamicSharedMemorySize, SMEM_DYN);
    cudaFuncSetAttribute(hgemm<1, false>, cudaFuncAttributeMaxDynamicSharedMemorySize, SMEM_DYN);
    cudaFuncSetAttribute(hgemm<2, true>,  cudaFuncAttributeMaxDynamicSharedMemorySize, SMEM_DYN);

    const long long LD = (long long)LLEN * DDIM;   // 2M
    const long long LLsq = (long long)LLEN * LLEN; // 4M

    // 1) convert inputs to fp16
    conv_k<<<MTOT * DDIM / 1024, 256>>>(q, q16);
    conv_k<<<MTOT * DDIM / 1024, 256>>>(k, k16);
    conv_k<<<MTOT * DDIM / 1024, 256>>>(v, v16);

    // 2) transpose + convert weights: W[K,N] -> Wt[N,K] fp16
    {
        dim3 b(32, 8);
        transpose_conv_k<<<dim3(32, 32), b>>>(Wq, WqT, DDIM, DDIM);
        transpose_conv_k<<<dim3(32, 32), b>>>(Wk, WkT, DDIM, DDIM);
        transpose_conv_k<<<dim3(32, 32), b>>>(Wv, WvT, DDIM, DDIM);
        transpose_conv_k<<<dim3(32, 64), b>>>(Wg, WgT, 2 * DDIM, DDIM);
    }

    // 3) projections: qp/kp/vp = in @ W + b  (M=16384, N=1024, K=1024)
    {
        dim3 g(DDIM / 128, MTOT / 128, 1);
        hgemm<0, false><<<g, 256, SMEM_DYN>>>(q16, nullptr, DDIM, 0, WqT, DDIM,
            bq, nullptr, qp, DDIM, DDIM, 0, 0, 0, 0.f, nullptr, nullptr, nullptr);
        hgemm<0, false><<<g, 256, SMEM_DYN>>>(k16, nullptr, DDIM, 0, WkT, DDIM,
            bk, nullptr, kp, DDIM, DDIM, 0, 0, 0, 0.f, nullptr, nullptr, nullptr);
        hgemm<0, false><<<g, 256, SMEM_DYN>>>(v16, nullptr, DDIM, 0, WvT, DDIM,
            bv, nullptr, vp, DDIM, DDIM, 0, 0, 0, 0.f, nullptr, nullptr, nullptr);
    }

    // 4) transpose vp [MTOT, D] -> vpT [D, MTOT]
    {
        dim3 b(32, 8);
        transpose_h_k<<<dim3(32, 512), b>>>(vp, vpT, MTOT, DDIM);
    }

    // 5) scores: S16[b] = (qp[b] @ kp[b]^T) / 32  (per batch 2048x2048, K=1024)
    {
        dim3 g(LLEN / 128, LLEN / 128, BB);
        hgemm<1, false><<<g, 256, SMEM_DYN>>>(qp, nullptr, DDIM, 0, kp, DDIM,
            nullptr, nullptr, S16, LLEN, DDIM, LD, LD, LLsq, 0.03125f,
            nullptr, nullptr, nullptr);
    }

    // 6) softmax -> P fp16 (vectorized)
    softmax_h_k<<<MTOT, 256>>>(S16, P);

    // 7) x[b] = P[b] @ vp[b]  (B operand = vpT slice, ldb = MTOT)
    {
        dim3 g(DDIM / 128, LLEN / 128, BB);
        hgemm<0, false><<<g, 256, SMEM_DYN>>>(P, nullptr, LLEN, 0, vpT, MTOT,
            nullptr, nullptr, x16, DDIM, LLEN, LLsq, LLEN, LD, 0.f,
            nullptr, nullptr, nullptr);
    }

    // 8) gate GEMM + fused epilogue -> d_out
    {
        dim3 g(DDIM / 128, MTOT / 128, 1);
        hgemm<2, true><<<g, 256, SMEM_DYN>>>(qp, x16, DDIM, DDIM, WgT, 2 * DDIM,
            bg, out, nullptr, DDIM, 2 * DDIM, 0, 0, 0, 0.f, x16, q, mask);
    }
}

// round 17
// speedup vs baseline: 1.4892x; 1.4892x over previous
#include <cuda_runtime.h>
#include <cuda_fp16.h>
#include <cstdint>
#include <math.h>

#define BB 8
#define LLEN 2048
#define DDIM 1024
#define MTOT (BB * LLEN)          // 16384

// ---------------------------------------------------------------------------
// Scratch (__device__ globals; allocation-free per harness rules)
// ---------------------------------------------------------------------------
__device__ __half g_q16[MTOT * DDIM], g_k16[MTOT * DDIM], g_v16[MTOT * DDIM];
__device__ __half g_WqT[DDIM * DDIM], g_WkT[DDIM * DDIM], g_WvT[DDIM * DDIM];
__device__ __half g_WgT[DDIM * 2 * DDIM];
__device__ __half g_qp[MTOT * DDIM], g_kp[MTOT * DDIM], g_vp[MTOT * DDIM];
__device__ __half g_vpT[MTOT * DDIM];
__device__ float  g_S[BB * LLEN * LLEN];          // 134 MB
__device__ __half g_P[BB * LLEN * LLEN];          // 67 MB
__device__ __half g_x16[MTOT * DDIM];

// ---------------------------------------------------------------------------
// helpers
// ---------------------------------------------------------------------------
__device__ __forceinline__ uint32_t smem_u32(const void* p) {
    uint32_t a;
    asm("{ .reg .u64 t; cvta.to.shared.u64 t, %1; cvt.u32.u64 %0, t; }"
        : "=r"(a) : "l"(p));
    return a;
}
__device__ __forceinline__ void cp16(uint32_t d, const void* s) {
    asm volatile("cp.async.cg.shared.global [%0], [%1], 16;"
                 :: "r"(d), "l"(s) : "memory");
}
__device__ __forceinline__ void cp_commit() {
    asm volatile("cp.async.commit_group;" ::: "memory");
}
template <int N>
__device__ __forceinline__ void cp_wait() {
    asm volatile("cp.async.wait_group %0;" :: "n"(N) : "memory");
}
__device__ __forceinline__ void ldsm4(uint32_t addr, uint32_t* r) {
    asm volatile("ldmatrix.sync.aligned.m8n8.x4.shared.b16 {%0,%1,%2,%3}, [%4];"
                 : "=r"(r[0]), "=r"(r[1]), "=r"(r[2]), "=r"(r[3]) : "r"(addr));
}
__device__ __forceinline__ void mma16816(float* c, const uint32_t* a,
                                         uint32_t b0, uint32_t b1) {
    asm volatile(
        "mma.sync.aligned.m16n8k16.row.col.f32.f16.f16.f32 "
        "{%0,%1,%2,%3}, {%4,%5,%6,%7}, {%8,%9}, {%0,%1,%2,%3};"
        : "+f"(c[0]), "+f"(c[1]), "+f"(c[2]), "+f"(c[3])
        : "r"(a[0]), "r"(a[1]), "r"(a[2]), "r"(a[3]), "r"(b0), "r"(b1));
}

#define SWZ(o) ((o) ^ (((o) >> 3) & 0x70))

__device__ __forceinline__ uint32_t h2pack(float a, float b) {
    __half2 h = __floats2half2_rn(a, b);
    return *(uint32_t*)&h;
}

// ---------------------------------------------------------------------------
// fp16 HMMA GEMM: C[M,N] = epi( A[M,K] @ B[N,K]^T ), single pass
//   CTA tile 128x128, BK=64, 3-stage cp.async pipeline, 8 warps (32x64 each)
//   2 CTAs/SM (96KB smem each).
//   EPI 0: +bias (nullable), write fp16
//   EPI 1: *alpha, write fp32
//   EPI 2: gate: out = x16*mask*sigmoid(acc+bias) + q0, write fp32
// ---------------------------------------------------------------------------
template <int EPI, bool CONCAT>
__global__ __launch_bounds__(256, 2)
void hgemm(const __half* __restrict__ A, const __half* __restrict__ A2,
           int lda, int KA,
           const __half* __restrict__ B, int ldb,
           const float* __restrict__ bias,
           float* __restrict__ Cf, __half* __restrict__ Ch,
           int ldc, int K,
           long long sA, long long sB, long long sC, float alpha,
           const __half* __restrict__ x16, const float* __restrict__ q0,
           const float* __restrict__ mask)
{
    extern __shared__ char dsm[];
    const uint32_t raw = smem_u32(dsm);
    const uint32_t abase = (raw + 1023u) & ~1023u;

    constexpr int TILE = 16384;                 // one 128x64 fp16 tile (swizzled)
    constexpr int OFF_A = 0;                    // 3 stages
    constexpr int OFF_B = 3 * TILE;

    const int tid = threadIdx.x, wid = tid >> 5, lid = tid & 31;
    const int bn = blockIdx.x, bm = blockIdx.y, bz = blockIdx.z;

    A += (long long)bz * sA;
    B += (long long)bz * sB;
    if (EPI == 1 || EPI == 2) Cf += (long long)bz * sC;
    if (EPI == 0) Ch += (long long)bz * sC;

    const int rowA0 = bm * 128, rowB0 = bn * 128;

    auto stage = [&](int kt, int buf) {
        const int r = tid >> 3, seg = tid & 7;
        long long kc = (long long)kt * 64 + seg * 8;
        const __half* pA = A;
        long long kA = kc;
        if (CONCAT && kc >= KA) { pA = A2; kA = kc - KA; }
        #pragma unroll
        for (int i = 0; i < 4; ++i) {
            const int rr = i * 32 + r;
            const uint32_t so = SWZ(rr * 128 + seg * 16);
            cp16(abase + OFF_A + buf * TILE + so, pA + (long long)(rowA0 + rr) * lda + kA);
            cp16(abase + OFF_B + buf * TILE + so, B + (long long)(rowB0 + rr) * ldb + kc);
        }
    };

    const int wm0 = (wid & 3) * 32;     // warp m offset (4 warps over 128)
    const int wn0 = (wid >> 2) * 64;    // warp n offset (2 warps over 128)
    const int r16 = lid & 15, hseg = lid >> 4;

    float acc[2][8][4] = {};

    const int nt = K / 64;
    stage(0, 0); cp_commit();
    stage(1, 1); cp_commit();

    for (int t = 0; t < nt; ++t) {
        if (t + 1 < nt) cp_wait<1>(); else cp_wait<0>();
        __syncthreads();
        if (t + 2 < nt) { stage(t + 2, (t + 2) % 3); cp_commit(); }

        const int buf = t % 3;
        const uint32_t ba = abase + OFF_A + buf * TILE;
        const uint32_t bb = abase + OFF_B + buf * TILE;

        #pragma unroll
        for (int s = 0; s < 4; ++s) {
            uint32_t a[2][4], b[4][4];
            #pragma unroll
            for (int mf = 0; mf < 2; ++mf) {
                const uint32_t o = (uint32_t)((wm0 + mf * 16 + r16) * 128 + s * 32 + hseg * 16);
                ldsm4(ba + SWZ(o), a[mf]);
            }
            #pragma unroll
            for (int g = 0; g < 4; ++g) {
                const uint32_t o = (uint32_t)((wn0 + g * 16 + r16) * 128 + s * 32 + hseg * 16);
                ldsm4(bb + SWZ(o), b[g]);
            }
            #pragma unroll
            for (int mf = 0; mf < 2; ++mf)
                #pragma unroll
                for (int nf = 0; nf < 8; ++nf) {
                    const int g = nf >> 1, o = nf & 1;
                    mma16816(acc[mf][nf], a[mf], b[g][o], b[g][o + 2]);
                }
        }
        // no trailing barrier: next iteration's cp_wait + barrier provide
        // ordering before any staging buffer is overwritten.
    }

    // ------------------- epilogue -------------------
    #pragma unroll
    for (int mf = 0; mf < 2; ++mf) {
        #pragma unroll
        for (int nf = 0; nf < 8; ++nf) {
            const int col = bn * 128 + wn0 + nf * 8 + (lid & 3) * 2;
            #pragma unroll
            for (int h = 0; h < 2; ++h) {
                const int row = bm * 128 + wm0 + mf * 16 + (lid >> 2) + h * 8;
                const long long off = (long long)row * ldc + col;
                float v0 = acc[mf][nf][h * 2 + 0];
                float v1 = acc[mf][nf][h * 2 + 1];

                if (EPI == 0) {
                    if (bias) {
                        const float2 b2 = *(const float2*)(bias + col);
                        v0 += b2.x; v1 += b2.y;
                    }
                    *(uint32_t*)(Ch + off) = h2pack(v0, v1);
                } else if (EPI == 1) {
                    *(float2*)(Cf + off) = make_float2(v0 * alpha, v1 * alpha);
                } else {
                    const float mv = mask[row];
                    const float2 b2 = *(const float2*)(bias + col);
                    const __half2 xh2 = *(const __half2*)(x16 + off);
                    const float2 xf = __half22float2(xh2);
                    const float2 q2 = *(const float2*)(q0 + off);
                    const float g0 = v0 + b2.x, g1 = v1 + b2.y;
                    const float s0 = 1.0f / (1.0f + __expf(-g0));
                    const float s1 = 1.0f / (1.0f + __expf(-g1));
                    *(float2*)(Cf + off) = make_float2(xf.x * mv * s0 + q2.x,
                                                       xf.y * mv * s1 + q2.y);
                }
            }
        }
    }
}

// ---------------------------------------------------------------------------
// fp32 -> fp16 convert (elementwise, 4/thread)
// ---------------------------------------------------------------------------
__global__ __launch_bounds__(256)
void conv_k(const float* __restrict__ X, __half* __restrict__ H)
{
    const long long i = ((long long)blockIdx.x * 256 + threadIdx.x) * 4;
    float4 v = *(const float4*)(X + i);
    uint2 o;
    o.x = h2pack(v.x, v.y);
    o.y = h2pack(v.z, v.w);
    *(uint2*)(H + i) = o;
}

// W[R,C] fp32 -> T[C,R] fp16 (transpose + convert)
__global__ __launch_bounds__(256)
void transpose_conv_k(const float* __restrict__ W, __half* __restrict__ T,
                      int R, int C)
{
    __shared__ float tile[32][33];
    const int tx = threadIdx.x, ty = threadIdx.y;
    const int x = blockIdx.x * 32 + tx;
    const int y0 = blockIdx.y * 32;
    #pragma unroll
    for (int j = ty; j < 32; j += 8)
        tile[j][tx] = W[(long long)(y0 + j) * C + x];
    __syncthreads();
    const int ox = y0 + tx;
    const int oy0 = blockIdx.x * 32;
    #pragma unroll
    for (int j = ty; j < 32; j += 8)
        T[(long long)(oy0 + j) * R + ox] = __float2half_rn(tile[tx][j]);
}

// fp16 transpose: X[R,C] -> T[C,R]
__global__ __launch_bounds__(256)
void transpose_h_k(const __half* __restrict__ X, __half* __restrict__ T,
                   int R, int C)
{
    __shared__ __half tile[32][34];
    const int tx = threadIdx.x, ty = threadIdx.y;
    const int x = blockIdx.x * 32 + tx;
    const int y0 = blockIdx.y * 32;
    #pragma unroll
    for (int j = ty; j < 32; j += 8)
        tile[j][tx] = X[(long long)(y0 + j) * C + x];
    __syncthreads();
    const int ox = y0 + tx;
    const int oy0 = blockIdx.x * 32;
    #pragma unroll
    for (int j = ty; j < 32; j += 8)
        T[(long long)(oy0 + j) * R + ox] = tile[tx][j];
}

// Row softmax over S (rows of 2048 fp32) -> P fp16
__global__ __launch_bounds__(256)
void softmax_h_k(const float* __restrict__ S, __half* __restrict__ P)
{
    const long long base = (long long)blockIdx.x * LLEN;
    const float* row = S + base;
    const int tid = threadIdx.x;

    float v[8];
    #pragma unroll
    for (int i = 0; i < 8; ++i) v[i] = row[tid + 256 * i];

    float mx = v[0];
    #pragma unroll
    for (int i = 1; i < 8; ++i) mx = fmaxf(mx, v[i]);
    #pragma unroll
    for (int o = 16; o > 0; o >>= 1)
        mx = fmaxf(mx, __shfl_xor_sync(0xffffffffu, mx, o));

    __shared__ float red[8];
    if ((tid & 31) == 0) red[tid >> 5] = mx;
    __syncthreads();
    mx = red[0];
    #pragma unroll
    for (int i = 1; i < 8; ++i) mx = fmaxf(mx, red[i]);
    __syncthreads();

    float s = 0.0f;
    #pragma unroll
    for (int i = 0; i < 8; ++i) { v[i] = __expf(v[i] - mx); s += v[i]; }
    #pragma unroll
    for (int o = 16; o > 0; o >>= 1)
        s += __shfl_xor_sync(0xffffffffu, s, o);
    if ((tid & 31) == 0) red[tid >> 5] = s;
    __syncthreads();
    s = 0.0f;
    #pragma unroll
    for (int i = 0; i < 8; ++i) s += red[i];

    const float inv = 1.0f / s;
    #pragma unroll
    for (int i = 0; i < 8; ++i)
        P[base + tid + 256 * i] = __float2half_rn(v[i] * inv);
}

// ---------------------------------------------------------------------------
// Host
// ---------------------------------------------------------------------------
extern "C" void kernel_launch(void* const* d_in, const int* in_sizes, int n_in,
                              void* d_out, int out_size)
{
    const float* q    = (const float*)d_in[0];
    const float* k    = (const float*)d_in[1];
    const float* v    = (const float*)d_in[2];
    const float* mask = (const float*)d_in[3];
    const float* Wq   = (const float*)d_in[4];
    const float* bq   = (const float*)d_in[5];
    const float* Wk   = (const float*)d_in[6];
    const float* bk   = (const float*)d_in[7];
    const float* Wv   = (const float*)d_in[8];
    const float* bv   = (const float*)d_in[9];
    const float* Wg   = (const float*)d_in[10];
    const float* bg   = (const float*)d_in[11];
    float* out = (float*)d_out;

    #define SYM(p, s) void* p##_; cudaGetSymbolAddress(&p##_, s); \
                      __half* p = (__half*)p##_;
    SYM(q16, g_q16) SYM(k16, g_k16) SYM(v16, g_v16)
    SYM(WqT, g_WqT) SYM(WkT, g_WkT) SYM(WvT, g_WvT) SYM(WgT, g_WgT)
    SYM(qp, g_qp)   SYM(kp, g_kp)   SYM(vp, g_vp)   SYM(vpT, g_vpT)
    SYM(P, g_P)     SYM(x16, g_x16)
    #undef SYM
    void* S_; cudaGetSymbolAddress(&S_, g_S); float* S = (float*)S_;

    const int SMEM_DYN = 6 * 16384 + 1024;   // 3 stages x (A+B) + align pad
    cudaFuncSetAttribute(hgemm<0, false>, cudaFuncAttributeMaxDynamicSharedMemorySize, SMEM_DYN);
    cudaFuncSetAttribute(hgemm<1, false>, cudaFuncAttributeMaxDynamicSharedMemorySize, SMEM_DYN);
    cudaFuncSetAttribute(hgemm<2, true>,  cudaFuncAttributeMaxDynamicSharedMemorySize, SMEM_DYN);

    const long long LD = (long long)LLEN * DDIM;   // 2M
    const long long LLsq = (long long)LLEN * LLEN; // 4M

    // 1) convert inputs to fp16
    conv_k<<<MTOT * DDIM / 1024, 256>>>(q, q16);
    conv_k<<<MTOT * DDIM / 1024, 256>>>(k, k16);
    conv_k<<<MTOT * DDIM / 1024, 256>>>(v, v16);

    // 2) transpose + convert weights: W[K,N] -> Wt[N,K] fp16
    {
        dim3 b(32, 8);
        transpose_conv_k<<<dim3(32, 32), b>>>(Wq, WqT, DDIM, DDIM);
        transpose_conv_k<<<dim3(32, 32), b>>>(Wk, WkT, DDIM, DDIM);
        transpose_conv_k<<<dim3(32, 32), b>>>(Wv, WvT, DDIM, DDIM);
        transpose_conv_k<<<dim3(32, 64), b>>>(Wg, WgT, 2 * DDIM, DDIM);
    }

    // 3) projections: qp/kp/vp = in @ W + b  (M=16384, N=1024, K=1024)
    {
        dim3 g(DDIM / 128, MTOT / 128, 1);
        hgemm<0, false><<<g, 256, SMEM_DYN>>>(q16, nullptr, DDIM, 0, WqT, DDIM,
            bq, nullptr, qp, DDIM, DDIM, 0, 0, 0, 0.f, nullptr, nullptr, nullptr);
        hgemm<0, false><<<g, 256, SMEM_DYN>>>(k16, nullptr, DDIM, 0, WkT, DDIM,
            bk, nullptr, kp, DDIM, DDIM, 0, 0, 0, 0.f, nullptr, nullptr, nullptr);
        hgemm<0, false><<<g, 256, SMEM_DYN>>>(v16, nullptr, DDIM, 0, WvT, DDIM,
            bv, nullptr, vp, DDIM, DDIM, 0, 0, 0, 0.f, nullptr, nullptr, nullptr);
    }

    // 4) transpose vp [MTOT, D] -> vpT [D, MTOT]
    {
        dim3 b(32, 8);
        transpose_h_k<<<dim3(32, 512), b>>>(vp, vpT, MTOT, DDIM);
    }

    // 5) scores: S[b] = (qp[b] @ kp[b]^T) / 32  (per batch 2048x2048, K=1024)
    {
        dim3 g(LLEN / 128, LLEN / 128, BB);
        hgemm<1, false><<<g, 256, SMEM_DYN>>>(qp, nullptr, DDIM, 0, kp, DDIM,
            nullptr, S, nullptr, LLEN, DDIM, LD, LD, LLsq, 0.03125f,
            nullptr, nullptr, nullptr);
    }

    // 6) softmax -> P fp16
    softmax_h_k<<<MTOT, 256>>>(S, P);

    // 7) x[b] = P[b] @ vp[b]  (B operand = vpT slice, ldb = MTOT)
    {
        dim3 g(DDIM / 128, LLEN / 128, BB);
        hgemm<0, false><<<g, 256, SMEM_DYN>>>(P, nullptr, LLEN, 0, vpT, MTOT,
            nullptr, nullptr, x16, DDIM, LLEN, LLsq, LLEN, LD, 0.f,
            nullptr, nullptr, nullptr);
    }

    // 8) gate GEMM + fused epilogue -> d_out
    {
        dim3 g(DDIM / 128, MTOT / 128, 1);
        hgemm<2, true><<<g, 256, SMEM_DYN>>>(qp, x16, DDIM, DDIM, WgT, 2 * DDIM,
            bg, out, nullptr, DDIM, 2 * DDIM, 0, 0, 0, 0.f, x16, q, mask);
    }
}